// round 14
// baseline (speedup 1.0000x reference)
#include <cuda_runtime.h>
#include <math.h>
#include <float.h>
#include <stdint.h>

#define NN 8192
#define DD 128
#define TOPK 30

typedef unsigned long long u64;

// ---- scratch (device globals; no runtime allocation allowed) ----
__device__ float g_M1t[DD * NN];              // M1^T  [128][8192]
__device__ float g_M2t[DD * NN];              // M2^T  [128][8192]

// ============================================================================
// packed f32x2 helpers (Blackwell sm_103a): 2 IEEE fp32 FMAs per issue slot.
// ============================================================================
__device__ __forceinline__ void fma2(u64& d, u64 a, u64 b) {
    asm("fma.rn.f32x2 %0, %1, %2, %0;" : "+l"(d) : "l"(a), "l"(b));
}
__device__ __forceinline__ u64 pack2(float x) {
    u64 r; asm("mov.b64 %0, {%1, %1};" : "=l"(r) : "f"(x)); return r;
}
__device__ __forceinline__ float2 unpk(u64 x) {
    float2 f; asm("mov.b64 {%0, %1}, %2;" : "=f"(f.x), "=f"(f.y) : "l"(x)); return f;
}

// ============================================================================
// XLA/Eigen f32 tanh replica (EmitTanh / generic_fast_tanh_float).
// ============================================================================
__device__ __forceinline__ float xla_tanh(float x) {
    const float kClamp = 7.90531110763549805f;
    const bool tiny = fabsf(x) < 0.0004f;
    float xc = fminf(fmaxf(x, -kClamp), kClamp);
    float x2 = xc * xc;
    float p = fmaf(x2, -2.76076847742355e-16f, 2.00018790482477e-13f);
    p = fmaf(x2, p, -8.60467152213735e-11f);
    p = fmaf(x2, p, 5.12229709037114e-08f);
    p = fmaf(x2, p, 1.48572235717979e-05f);
    p = fmaf(x2, p, 6.37261928875436e-04f);
    p = fmaf(x2, p, 4.89352455891786e-03f);
    p = xc * p;
    float q = fmaf(x2, 1.19825839466702e-06f, 1.18534705686654e-04f);
    q = fmaf(x2, q, 2.26843463243900e-03f);
    q = fmaf(x2, q, 4.89352518554385e-03f);
    float r = __fdiv_rn(p, q);
    return tiny ? x : r;
}

// ============================================================================
// Kernel 1 (round-9, unchanged): M = tanh(3*(E @ W^T + b)); transposed store.
// ============================================================================
__global__ void prep_kernel(const float* __restrict__ E1,
                            const float* __restrict__ W1,
                            const float* __restrict__ b1,
                            const float* __restrict__ E2,
                            const float* __restrict__ W2,
                            const float* __restrict__ b2)
{
    extern __shared__ float sh[];
    float* Ws = sh;               // 128 rows x 128 (swizzled)
    float* Es = sh + DD * DD;     // 32 rows x 128 (swizzled)
    __shared__ float bs[DD];

    const int mode = blockIdx.y;
    const float* __restrict__ E = mode ? E2 : E1;
    const float* __restrict__ W = mode ? W2 : W1;
    const float* __restrict__ b = mode ? b2 : b1;
    float* __restrict__ Mt = mode ? g_M2t : g_M1t;

    const int tid = threadIdx.x;
    const int row0 = blockIdx.x * 32;

    {
        const float4* W4 = (const float4*)W;
        #pragma unroll 4
        for (int i = tid; i < DD * DD / 4; i += 256) {
            const int rowm = i >> 5, q = i & 31;
            float4 v = W4[i];
            *(float4*)&Ws[rowm * DD + ((4 * q + 4 * (rowm >> 2)) & 127)] = v;
        }
        const float4* E4 = (const float4*)(E + (size_t)row0 * DD);
        #pragma unroll
        for (int i = tid; i < 32 * DD / 4; i += 256) {
            const int rowm = i >> 5, q = i & 31;
            float4 v = E4[i];
            *(float4*)&Es[rowm * DD + ((4 * q + 4 * (rowm >> 2)) & 127)] = v;
        }
        if (tid < DD) bs[tid] = b[tid];
    }
    __syncthreads();

    const int tx = tid & 7;
    const int ty = tid >> 3;

    float acc[4][4];
    #pragma unroll
    for (int r = 0; r < 4; r++)
        #pragma unroll
        for (int c = 0; c < 4; c++) acc[r][c] = 0.0f;

    #pragma unroll 8
    for (int k = 0; k < DD; k += 4) {
        const int ke = (k + 4 * tx) & 127;
        const int kw = (k + 4 * ty) & 127;
        float4 ev[4], wv[4];
        #pragma unroll
        for (int r = 0; r < 4; r++) ev[r] = *(const float4*)&Es[(tx * 4 + r) * DD + ke];
        #pragma unroll
        for (int c = 0; c < 4; c++) wv[c] = *(const float4*)&Ws[(ty * 4 + c) * DD + kw];
        #pragma unroll
        for (int r = 0; r < 4; r++)
            #pragma unroll
            for (int c = 0; c < 4; c++) {
                acc[r][c] = fmaf(ev[r].x, wv[c].x, acc[r][c]);
                acc[r][c] = fmaf(ev[r].y, wv[c].y, acc[r][c]);
                acc[r][c] = fmaf(ev[r].z, wv[c].z, acc[r][c]);
                acc[r][c] = fmaf(ev[r].w, wv[c].w, acc[r][c]);
            }
    }

    #pragma unroll
    for (int c = 0; c < 4; c++) {
        const int d = ty * 4 + c;
        float m[4];
        #pragma unroll
        for (int r = 0; r < 4; r++) {
            const float t = acc[r][c] + bs[d];
            const float u = 3.0f * t;
            m[r] = xla_tanh(u);
        }
        const int rowb = row0 + tx * 4;
        float4 v; v.x = m[0]; v.y = m[1]; v.z = m[2]; v.w = m[3];
        *(float4*)&Mt[(size_t)d * NN + rowb] = v;
    }
}

// ============================================================================
// Kernel 2 (round-9 version, FROZEN): 128x64 tile, 2 CTAs/SM, row-paired
// f32x2 FMA chains, bit-exact ascending-k. bj >= 2*bi tiles only.
// dyn smem = 49152 B.
// ============================================================================
#define BK 16
#define NCHUNK (DD / BK)
#define ARR_I (BK * 128)
#define ARR_J (BK * 64)
#define BUF (2 * ARR_I + 2 * ARR_J)

__device__ __forceinline__ void cp16(uint32_t smem_dst, const float* gsrc) {
    asm volatile("cp.async.ca.shared.global [%0], [%1], 16;\n"
                 :: "r"(smem_dst), "l"(gsrc));
}

__global__ void __launch_bounds__(256, 2) gemm_kernel(float* __restrict__ aout)
{
    const int bi = blockIdx.y;
    const int bj = blockIdx.x;
    if (bj < 2 * bi) return;

    extern __shared__ float sh[];

    const int I0 = bi * 128, J0 = bj * 64;
    const int tid = threadIdx.x;
    const int tx = tid & 15;
    const int ty = tid >> 4;

    const uint32_t sbase = (uint32_t)__cvta_generic_to_shared(sh);

    auto issue_chunk = [&](int c, int buf) {
        const int kb = c * BK;
        #pragma unroll
        for (int j = 0; j < 4; j++) {
            const int f = tid + 256 * j;
            const int arr = f >> 9;
            const int idx = f & 511;
            const int kk = idx >> 5, q = idx & 31;
            const float* src = (arr ? g_M2t : g_M1t) + (size_t)(kb + kk) * NN + I0 + q * 4;
            cp16(sbase + (uint32_t)((buf * BUF + arr * ARR_I + kk * 128 + q * 4) * 4), src);
        }
        {
            const int kk = tid >> 4, q = tid & 15;
            const size_t gk = (size_t)(kb + kk) * NN + J0 + q * 4;
            cp16(sbase + (uint32_t)((buf * BUF + 2 * ARR_I + kk * 64 + q * 4) * 4), g_M1t + gk);
            cp16(sbase + (uint32_t)((buf * BUF + 2 * ARR_I + ARR_J + kk * 64 + q * 4) * 4), g_M2t + gk);
        }
        asm volatile("cp.async.commit_group;\n");
    };

    issue_chunk(0, 0);

    u64 accP[4][4], accQ[4][4];
    #pragma unroll
    for (int r = 0; r < 4; r++)
        #pragma unroll
        for (int c = 0; c < 4; c++) { accP[r][c] = 0ULL; accQ[r][c] = 0ULL; }

    for (int c = 0; c < NCHUNK; c++) {
        const int cur = c & 1;
        if (c < NCHUNK - 1) {
            issue_chunk(c + 1, cur ^ 1);
            asm volatile("cp.async.wait_group 1;\n");
        } else {
            asm volatile("cp.async.wait_group 0;\n");
        }
        __syncthreads();

        const float* M1I = sh + cur * BUF;
        const float* M2I = sh + cur * BUF + ARR_I;
        const float* M1J = sh + cur * BUF + 2 * ARR_I;
        const float* M2J = sh + cur * BUF + 2 * ARR_I + ARR_J;

        #pragma unroll
        for (int kk = 0; kk < BK; kk++) {
            ulonglong2 a1lo = *(const ulonglong2*)&M1I[kk * 128 + ty * 8];
            ulonglong2 a1hi = *(const ulonglong2*)&M1I[kk * 128 + ty * 8 + 4];
            ulonglong2 a2lo = *(const ulonglong2*)&M2I[kk * 128 + ty * 8];
            ulonglong2 a2hi = *(const ulonglong2*)&M2I[kk * 128 + ty * 8 + 4];
            u64 a1p[4] = { a1lo.x, a1lo.y, a1hi.x, a1hi.y };
            u64 a2p[4] = { a2lo.x, a2lo.y, a2hi.x, a2hi.y };
            float4 f1 = *(const float4*)&M1J[kk * 64 + tx * 4];
            float4 f2 = *(const float4*)&M2J[kk * 64 + tx * 4];
            u64 b1d[4] = { pack2(f1.x), pack2(f1.y), pack2(f1.z), pack2(f1.w) };
            u64 b2d[4] = { pack2(f2.x), pack2(f2.y), pack2(f2.z), pack2(f2.w) };
            #pragma unroll
            for (int rp = 0; rp < 4; rp++)
                #pragma unroll
                for (int cc = 0; cc < 4; cc++) {
                    fma2(accP[rp][cc], a1p[rp], b2d[cc]);
                    fma2(accQ[rp][cc], a2p[rp], b1d[cc]);
                }
        }
        __syncthreads();
    }

    float P[8][4], Q[8][4];
    #pragma unroll
    for (int rp = 0; rp < 4; rp++)
        #pragma unroll
        for (int cc = 0; cc < 4; cc++) {
            float2 fp = unpk(accP[rp][cc]);
            float2 fq = unpk(accQ[rp][cc]);
            P[2*rp][cc] = fp.x; P[2*rp+1][cc] = fp.y;
            Q[2*rp][cc] = fq.x; Q[2*rp+1][cc] = fq.y;
        }

    const int ibase = I0 + ty * 8;
    const int jbase = J0 + tx * 4;
    const bool cross = ((bj >> 1) == bi);

    if (!cross) {
        #pragma unroll
        for (int r = 0; r < 8; r++) {
            float4 w;
            w.x = fmaxf(P[r][0] - Q[r][0], 0.0f);
            w.y = fmaxf(P[r][1] - Q[r][1], 0.0f);
            w.z = fmaxf(P[r][2] - Q[r][2], 0.0f);
            w.w = fmaxf(P[r][3] - Q[r][3], 0.0f);
            *(float4*)&aout[(size_t)(ibase + r) * NN + jbase] = w;
        }
        #pragma unroll
        for (int cc = 0; cc < 4; cc++) {
            const int jg = jbase + cc;
            float4 w0, w1;
            w0.x = fmaxf(Q[0][cc] - P[0][cc], 0.0f);
            w0.y = fmaxf(Q[1][cc] - P[1][cc], 0.0f);
            w0.z = fmaxf(Q[2][cc] - P[2][cc], 0.0f);
            w0.w = fmaxf(Q[3][cc] - P[3][cc], 0.0f);
            w1.x = fmaxf(Q[4][cc] - P[4][cc], 0.0f);
            w1.y = fmaxf(Q[5][cc] - P[5][cc], 0.0f);
            w1.z = fmaxf(Q[6][cc] - P[6][cc], 0.0f);
            w1.w = fmaxf(Q[7][cc] - P[7][cc], 0.0f);
            *(float4*)&aout[(size_t)jg * NN + ibase] = w0;
            *(float4*)&aout[(size_t)jg * NN + ibase + 4] = w1;
        }
    } else {
        #pragma unroll
        for (int r = 0; r < 8; r++) {
            const int ig = ibase + r;
            #pragma unroll
            for (int cc = 0; cc < 4; cc++) {
                const int jg = jbase + cc;
                if (jg > ig) {
                    aout[(size_t)ig * NN + jg] = fmaxf(P[r][cc] - Q[r][cc], 0.0f);
                    aout[(size_t)jg * NN + ig] = fmaxf(Q[r][cc] - P[r][cc], 0.0f);
                } else if (jg == ig) {
                    aout[(size_t)ig * NN + jg] = 0.0f;
                }
            }
        }
    }
}

// ============================================================================
// Kernel 3: per-row top-30. Float-domain prefilter (cheap), u64 exact keys
// only for candidates. Tv = rank-29 VALUE of per-lane top-2 set (subset
// bound: Tv <= true rank-29 value => {v >= Tv} contains the true top-30 and
// count >= 30; float ties only widen the set). cnt<=64: u64 sort of
// candidates (exact jax tie semantics). Else: exact u64 taken-mask argmax.
// ============================================================================
__device__ __forceinline__ u64 shfl64_xor(u64 x, int off) {
    return __shfl_xor_sync(0xffffffffu, x, off);
}

// warp-collective bitonic sort (descending) of 64 u64 keys, 2/lane.
__device__ __forceinline__ void warp_sort64_desc(u64& e0, u64& e1, int lane) {
    #pragma unroll
    for (int size = 2; size <= 64; size <<= 1) {
        #pragma unroll
        for (int stride = size >> 1; stride > 0; stride >>= 1) {
            const bool desc = (((2 * lane) & size) == 0);
            if (stride == 1) {
                const u64 lo = (e0 < e1) ? e0 : e1;
                const u64 hi = (e0 < e1) ? e1 : e0;
                e0 = desc ? hi : lo;
                e1 = desc ? lo : hi;
            } else {
                const int half = stride >> 1;
                const u64 p0 = shfl64_xor(e0, half);
                const u64 p1 = shfl64_xor(e1, half);
                const bool first = (((2 * lane) & stride) == 0);
                const bool keepmax = (first == desc);
                e0 = keepmax ? (e0 > p0 ? e0 : p0) : (e0 < p0 ? e0 : p0);
                e1 = keepmax ? (e1 > p1 ? e1 : p1) : (e1 < p1 ? e1 : p1);
            }
        }
    }
}

// warp-collective bitonic sort (descending) of 64 floats, 2/lane (1 shfl/stage).
__device__ __forceinline__ void warp_sort64f_desc(float& e0, float& e1, int lane) {
    #pragma unroll
    for (int size = 2; size <= 64; size <<= 1) {
        #pragma unroll
        for (int stride = size >> 1; stride > 0; stride >>= 1) {
            const bool desc = (((2 * lane) & size) == 0);
            if (stride == 1) {
                const float lo = fminf(e0, e1);
                const float hi = fmaxf(e0, e1);
                e0 = desc ? hi : lo;
                e1 = desc ? lo : hi;
            } else {
                const int half = stride >> 1;
                const float p0 = __shfl_xor_sync(0xffffffffu, e0, half);
                const float p1 = __shfl_xor_sync(0xffffffffu, e1, half);
                const bool first = (((2 * lane) & stride) == 0);
                const bool keepmax = (first == desc);
                e0 = keepmax ? fmaxf(e0, p0) : fminf(e0, p0);
                e1 = keepmax ? fmaxf(e1, p1) : fminf(e1, p1);
            }
        }
    }
}

__global__ void __launch_bounds__(256) topk_kernel(float* __restrict__ out,
                                                   long long abase,
                                                   int write_edges)
{
    __shared__ float vlist[8][1024];      // 32 KB
    __shared__ u64 cand[8][64];           // 4 KB
    __shared__ u64 wtop[8][TOPK];
    __shared__ u64 topkeys[TOPK];

    const int row = blockIdx.x;
    const int tid = threadIdx.x;
    const int lane = tid & 31;
    const int w = tid >> 5;
    float* arow = out + abase + (size_t)row * NN;

    // load row, zero it, stash values; track per-lane top-2 VALUES (cheap)
    float m1v = -1.0f, m2v = -1.0f;   // A values are >= 0
    const float4 z4 = make_float4(0.f, 0.f, 0.f, 0.f);
    #pragma unroll
    for (int q = 0; q < 8; q++) {
        const int base = (tid + 256 * q) * 4;
        float4 t = *(const float4*)&arow[base];
        *(float4*)&arow[base] = z4;
        const float vv[4] = { t.x, t.y, t.z, t.w };
        #pragma unroll
        for (int c = 0; c < 4; c++) {
            vlist[w][(q * 4 + c) * 32 + lane] = vv[c];
            const float v = vv[c];
            const bool g = v > m1v;
            const float nm2 = g ? m1v : fmaxf(v, m2v);
            m1v = g ? v : m1v;
            m2v = nm2;
        }
    }

    // Tv = rank-29 (0-based) VALUE of the warp's 64 lane-top-2 values
    warp_sort64f_desc(m1v, m2v, lane);
    const float Tv = __shfl_sync(0xffffffffu, m2v, 14);   // v-index 29

    cand[w][2 * lane] = 0ULL;
    cand[w][2 * lane + 1] = 0ULL;
    __syncwarp();

    // count + ballot-compact candidates with v >= Tv (float compare; u64 key
    // built only for hits)
    int cnt = 0;
    const unsigned lml = (1u << lane) - 1u;
    #pragma unroll
    for (int i = 0; i < 32; i++) {
        const float v = vlist[w][i * 32 + lane];
        const bool p = (v >= Tv);
        const unsigned msk = __ballot_sync(0xffffffffu, p);
        if (p) {
            const int col = 128 * w + 1024 * (i >> 2) + 4 * lane + (i & 3);
            const u64 key = ((u64)__float_as_uint(v) << 13) | (u64)(8191 - col);
            const int pos = cnt + __popc(msk & lml);
            if (pos < 64) cand[w][pos] = key;
        }
        cnt += __popc(msk);
    }
    __syncwarp();

    if (cnt <= 64) {
        // exact u64 sort of candidates (0-padded); first 30 = warp top-30
        u64 t0 = cand[w][2 * lane];
        u64 t1 = cand[w][2 * lane + 1];
        warp_sort64_desc(t0, t1, lane);
        if (lane < 15) {
            wtop[w][2 * lane] = t0;
            wtop[w][2 * lane + 1] = t1;
        }
    } else {
        // rare exact fallback: 30 iterations of warp argmax w/ taken mask
        unsigned taken = 0u;
        for (int it = 0; it < TOPK; it++) {
            u64 best = 0ULL;
            int besti = 0;
            #pragma unroll
            for (int i = 0; i < 32; i++) {
                if (!(taken & (1u << i))) {
                    const float v = vlist[w][i * 32 + lane];
                    const int col = 128 * w + 1024 * (i >> 2) + 4 * lane + (i & 3);
                    const u64 key = ((u64)__float_as_uint(v) << 13) | (u64)(8191 - col);
                    if (key > best) { best = key; besti = i; }
                }
            }
            u64 m = best;
            #pragma unroll
            for (int off = 16; off; off >>= 1) {
                const u64 om = shfl64_xor(m, off);
                if (om > m) m = om;
            }
            if (lane == 0) wtop[w][it] = m;
            if (best == m) taken |= (1u << besti);
        }
    }
    __syncthreads();

    // final merge: warp 0, lanes 0..7 hold sorted 30-list heads
    if (w == 0) {
        int h = 0;
        u64 head = (lane < 8) ? wtop[lane][0] : 0ULL;
        for (int it = 0; it < TOPK; it++) {
            u64 m = head;
            #pragma unroll
            for (int off = 4; off; off >>= 1) {
                const u64 om = shfl64_xor(m, off);
                if (om > m) m = om;
            }
            if (lane == 0) topkeys[it] = m;
            if (lane < 8 && head == m) {
                h++;
                head = (h < TOPK) ? wtop[lane][h] : 0ULL;
            }
        }
    }
    __syncthreads();

    if (tid < TOPK) {
        const u64 key = topkeys[tid];
        const float val = __uint_as_float((unsigned)(key >> 13));
        const int dst = 8191 - (int)(key & 8191);
        arow[dst] = val;
        if (write_edges) {
            const long long e = (long long)row * TOPK + tid;
            out[e] = (float)row;                                // src
            out[(long long)NN * TOPK + e] = (float)dst;         // dst
            out[2LL * NN * TOPK + e] = val;                     // attr
        }
    }
}

// ============================================================================
// launch
// ============================================================================
extern "C" void kernel_launch(void* const* d_in, const int* in_sizes, int n_in,
                              void* d_out, int out_size)
{
    const float* E1 = (const float*)d_in[0];
    const float* E2 = (const float*)d_in[1];
    const float* W1 = (const float*)d_in[2];
    const float* b1 = (const float*)d_in[3];
    const float* W2 = (const float*)d_in[4];
    const float* b2 = (const float*)d_in[5];
    float* out = (float*)d_out;

    cudaFuncSetAttribute(prep_kernel, cudaFuncAttributeMaxDynamicSharedMemorySize, 81920);
    cudaFuncSetAttribute(gemm_kernel, cudaFuncAttributeMaxDynamicSharedMemorySize, 49152);

    long long abase;
    int write_edges;
    if (out_size == (long long)NN * NN) { abase = 0; write_edges = 0; }
    else { abase = 3LL * NN * TOPK; write_edges = 1; }

    prep_kernel<<<dim3(NN / 32, 2), 256, 81920>>>(E1, W1, b1, E2, W2, b2);
    gemm_kernel<<<dim3(128, 64), 256, 49152>>>(out + abase);
    topk_kernel<<<NN, 256>>>(out, abase, write_edges);
}

// round 15
// speedup vs baseline: 1.1397x; 1.1397x over previous
#include <cuda_runtime.h>
#include <math.h>
#include <float.h>
#include <stdint.h>

#define NN 8192
#define DD 128
#define TOPK 30

typedef unsigned long long u64;

// ---- scratch (device globals; no runtime allocation allowed) ----
__device__ float g_M1t[DD * NN];              // M1^T  [128][8192]
__device__ float g_M2t[DD * NN];              // M2^T  [128][8192]

// ============================================================================
// packed f32x2 helpers (Blackwell sm_103a): 2 IEEE fp32 FMAs per issue slot.
// ============================================================================
__device__ __forceinline__ void fma2(u64& d, u64 a, u64 b) {
    asm("fma.rn.f32x2 %0, %1, %2, %0;" : "+l"(d) : "l"(a), "l"(b));
}
__device__ __forceinline__ u64 pack2(float x) {
    u64 r; asm("mov.b64 %0, {%1, %1};" : "=l"(r) : "f"(x)); return r;
}
__device__ __forceinline__ float2 unpk(u64 x) {
    float2 f; asm("mov.b64 {%0, %1}, %2;" : "=f"(f.x), "=f"(f.y) : "l"(x)); return f;
}

// ============================================================================
// XLA/Eigen f32 tanh replica (EmitTanh / generic_fast_tanh_float).
// ============================================================================
__device__ __forceinline__ float xla_tanh(float x) {
    const float kClamp = 7.90531110763549805f;
    const bool tiny = fabsf(x) < 0.0004f;
    float xc = fminf(fmaxf(x, -kClamp), kClamp);
    float x2 = xc * xc;
    float p = fmaf(x2, -2.76076847742355e-16f, 2.00018790482477e-13f);
    p = fmaf(x2, p, -8.60467152213735e-11f);
    p = fmaf(x2, p, 5.12229709037114e-08f);
    p = fmaf(x2, p, 1.48572235717979e-05f);
    p = fmaf(x2, p, 6.37261928875436e-04f);
    p = fmaf(x2, p, 4.89352455891786e-03f);
    p = xc * p;
    float q = fmaf(x2, 1.19825839466702e-06f, 1.18534705686654e-04f);
    q = fmaf(x2, q, 2.26843463243900e-03f);
    q = fmaf(x2, q, 4.89352518554385e-03f);
    float r = __fdiv_rn(p, q);
    return tiny ? x : r;
}

// ============================================================================
// Kernel 1 (round-9, unchanged): M = tanh(3*(E @ W^T + b)); transposed store.
// ============================================================================
__global__ void prep_kernel(const float* __restrict__ E1,
                            const float* __restrict__ W1,
                            const float* __restrict__ b1,
                            const float* __restrict__ E2,
                            const float* __restrict__ W2,
                            const float* __restrict__ b2)
{
    extern __shared__ float sh[];
    float* Ws = sh;               // 128 rows x 128 (swizzled)
    float* Es = sh + DD * DD;     // 32 rows x 128 (swizzled)
    __shared__ float bs[DD];

    const int mode = blockIdx.y;
    const float* __restrict__ E = mode ? E2 : E1;
    const float* __restrict__ W = mode ? W2 : W1;
    const float* __restrict__ b = mode ? b2 : b1;
    float* __restrict__ Mt = mode ? g_M2t : g_M1t;

    const int tid = threadIdx.x;
    const int row0 = blockIdx.x * 32;

    {
        const float4* W4 = (const float4*)W;
        #pragma unroll 4
        for (int i = tid; i < DD * DD / 4; i += 256) {
            const int rowm = i >> 5, q = i & 31;
            float4 v = W4[i];
            *(float4*)&Ws[rowm * DD + ((4 * q + 4 * (rowm >> 2)) & 127)] = v;
        }
        const float4* E4 = (const float4*)(E + (size_t)row0 * DD);
        #pragma unroll
        for (int i = tid; i < 32 * DD / 4; i += 256) {
            const int rowm = i >> 5, q = i & 31;
            float4 v = E4[i];
            *(float4*)&Es[rowm * DD + ((4 * q + 4 * (rowm >> 2)) & 127)] = v;
        }
        if (tid < DD) bs[tid] = b[tid];
    }
    __syncthreads();

    const int tx = tid & 7;
    const int ty = tid >> 3;

    float acc[4][4];
    #pragma unroll
    for (int r = 0; r < 4; r++)
        #pragma unroll
        for (int c = 0; c < 4; c++) acc[r][c] = 0.0f;

    #pragma unroll 8
    for (int k = 0; k < DD; k += 4) {
        const int ke = (k + 4 * tx) & 127;
        const int kw = (k + 4 * ty) & 127;
        float4 ev[4], wv[4];
        #pragma unroll
        for (int r = 0; r < 4; r++) ev[r] = *(const float4*)&Es[(tx * 4 + r) * DD + ke];
        #pragma unroll
        for (int c = 0; c < 4; c++) wv[c] = *(const float4*)&Ws[(ty * 4 + c) * DD + kw];
        #pragma unroll
        for (int r = 0; r < 4; r++)
            #pragma unroll
            for (int c = 0; c < 4; c++) {
                acc[r][c] = fmaf(ev[r].x, wv[c].x, acc[r][c]);
                acc[r][c] = fmaf(ev[r].y, wv[c].y, acc[r][c]);
                acc[r][c] = fmaf(ev[r].z, wv[c].z, acc[r][c]);
                acc[r][c] = fmaf(ev[r].w, wv[c].w, acc[r][c]);
            }
    }

    #pragma unroll
    for (int c = 0; c < 4; c++) {
        const int d = ty * 4 + c;
        float m[4];
        #pragma unroll
        for (int r = 0; r < 4; r++) {
            const float t = acc[r][c] + bs[d];
            const float u = 3.0f * t;
            m[r] = xla_tanh(u);
        }
        const int rowb = row0 + tx * 4;
        float4 v; v.x = m[0]; v.y = m[1]; v.z = m[2]; v.w = m[3];
        *(float4*)&Mt[(size_t)d * NN + rowb] = v;
    }
}

// ============================================================================
// Kernel 2 (round-9 body; single change: BK 16 -> 32, halving barrier/drain
// episodes 8 -> 4). 128x64 tile, 2 CTAs/SM, row-paired f32x2 FMA chains,
// bit-exact ascending-k. bj >= 2*bi tiles only. dyn smem = 98304 B.
// ============================================================================
#define BK 32
#define NCHUNK (DD / BK)          // 4
#define ARR_I (BK * 128)          // 4096 floats
#define ARR_J (BK * 64)           // 2048 floats
#define BUF (2 * ARR_I + 2 * ARR_J)   // 12288 floats per buffer

__device__ __forceinline__ void cp16(uint32_t smem_dst, const float* gsrc) {
    asm volatile("cp.async.ca.shared.global [%0], [%1], 16;\n"
                 :: "r"(smem_dst), "l"(gsrc));
}

__global__ void __launch_bounds__(256, 2) gemm_kernel(float* __restrict__ aout)
{
    const int bi = blockIdx.y;
    const int bj = blockIdx.x;
    if (bj < 2 * bi) return;

    extern __shared__ float sh[];

    const int I0 = bi * 128, J0 = bj * 64;
    const int tid = threadIdx.x;
    const int tx = tid & 15;
    const int ty = tid >> 4;

    const uint32_t sbase = (uint32_t)__cvta_generic_to_shared(sh);

    auto issue_chunk = [&](int c, int buf) {
        const int kb = c * BK;
        // I-side: 2 arrays x 32 kk x 32 quads = 2048 float4 (8 per thread)
        #pragma unroll
        for (int j = 0; j < 8; j++) {
            const int f = tid + 256 * j;
            const int arr = f >> 10;
            const int idx = f & 1023;
            const int kk = idx >> 5, q = idx & 31;
            const float* src = (arr ? g_M2t : g_M1t) + (size_t)(kb + kk) * NN + I0 + q * 4;
            cp16(sbase + (uint32_t)((buf * BUF + arr * ARR_I + kk * 128 + q * 4) * 4), src);
        }
        // J-side: 2 arrays x 32 kk x 16 quads = 1024 float4 (4 per thread)
        #pragma unroll
        for (int j = 0; j < 4; j++) {
            const int f = tid + 256 * j;
            const int arr = f >> 9;
            const int idx = f & 511;
            const int kk = idx >> 4, q = idx & 15;
            const float* src = (arr ? g_M2t : g_M1t) + (size_t)(kb + kk) * NN + J0 + q * 4;
            cp16(sbase + (uint32_t)((buf * BUF + 2 * ARR_I + arr * ARR_J + kk * 64 + q * 4) * 4), src);
        }
        asm volatile("cp.async.commit_group;\n");
    };

    issue_chunk(0, 0);

    u64 accP[4][4], accQ[4][4];
    #pragma unroll
    for (int r = 0; r < 4; r++)
        #pragma unroll
        for (int c = 0; c < 4; c++) { accP[r][c] = 0ULL; accQ[r][c] = 0ULL; }

    for (int c = 0; c < NCHUNK; c++) {
        const int cur = c & 1;
        if (c < NCHUNK - 1) {
            issue_chunk(c + 1, cur ^ 1);
            asm volatile("cp.async.wait_group 1;\n");
        } else {
            asm volatile("cp.async.wait_group 0;\n");
        }
        __syncthreads();

        const float* M1I = sh + cur * BUF;
        const float* M2I = sh + cur * BUF + ARR_I;
        const float* M1J = sh + cur * BUF + 2 * ARR_I;
        const float* M2J = sh + cur * BUF + 2 * ARR_I + ARR_J;

        #pragma unroll
        for (int kk = 0; kk < BK; kk++) {
            ulonglong2 a1lo = *(const ulonglong2*)&M1I[kk * 128 + ty * 8];
            ulonglong2 a1hi = *(const ulonglong2*)&M1I[kk * 128 + ty * 8 + 4];
            ulonglong2 a2lo = *(const ulonglong2*)&M2I[kk * 128 + ty * 8];
            ulonglong2 a2hi = *(const ulonglong2*)&M2I[kk * 128 + ty * 8 + 4];
            u64 a1p[4] = { a1lo.x, a1lo.y, a1hi.x, a1hi.y };
            u64 a2p[4] = { a2lo.x, a2lo.y, a2hi.x, a2hi.y };
            float4 f1 = *(const float4*)&M1J[kk * 64 + tx * 4];
            float4 f2 = *(const float4*)&M2J[kk * 64 + tx * 4];
            u64 b1d[4] = { pack2(f1.x), pack2(f1.y), pack2(f1.z), pack2(f1.w) };
            u64 b2d[4] = { pack2(f2.x), pack2(f2.y), pack2(f2.z), pack2(f2.w) };
            #pragma unroll
            for (int rp = 0; rp < 4; rp++)
                #pragma unroll
                for (int cc = 0; cc < 4; cc++) {
                    fma2(accP[rp][cc], a1p[rp], b2d[cc]);
                    fma2(accQ[rp][cc], a2p[rp], b1d[cc]);
                }
        }
        __syncthreads();
    }

    float P[8][4], Q[8][4];
    #pragma unroll
    for (int rp = 0; rp < 4; rp++)
        #pragma unroll
        for (int cc = 0; cc < 4; cc++) {
            float2 fp = unpk(accP[rp][cc]);
            float2 fq = unpk(accQ[rp][cc]);
            P[2*rp][cc] = fp.x; P[2*rp+1][cc] = fp.y;
            Q[2*rp][cc] = fq.x; Q[2*rp+1][cc] = fq.y;
        }

    const int ibase = I0 + ty * 8;
    const int jbase = J0 + tx * 4;
    const bool cross = ((bj >> 1) == bi);

    if (!cross) {
        #pragma unroll
        for (int r = 0; r < 8; r++) {
            float4 w;
            w.x = fmaxf(P[r][0] - Q[r][0], 0.0f);
            w.y = fmaxf(P[r][1] - Q[r][1], 0.0f);
            w.z = fmaxf(P[r][2] - Q[r][2], 0.0f);
            w.w = fmaxf(P[r][3] - Q[r][3], 0.0f);
            *(float4*)&aout[(size_t)(ibase + r) * NN + jbase] = w;
        }
        #pragma unroll
        for (int cc = 0; cc < 4; cc++) {
            const int jg = jbase + cc;
            float4 w0, w1;
            w0.x = fmaxf(Q[0][cc] - P[0][cc], 0.0f);
            w0.y = fmaxf(Q[1][cc] - P[1][cc], 0.0f);
            w0.z = fmaxf(Q[2][cc] - P[2][cc], 0.0f);
            w0.w = fmaxf(Q[3][cc] - P[3][cc], 0.0f);
            w1.x = fmaxf(Q[4][cc] - P[4][cc], 0.0f);
            w1.y = fmaxf(Q[5][cc] - P[5][cc], 0.0f);
            w1.z = fmaxf(Q[6][cc] - P[6][cc], 0.0f);
            w1.w = fmaxf(Q[7][cc] - P[7][cc], 0.0f);
            *(float4*)&aout[(size_t)jg * NN + ibase] = w0;
            *(float4*)&aout[(size_t)jg * NN + ibase + 4] = w1;
        }
    } else {
        #pragma unroll
        for (int r = 0; r < 8; r++) {
            const int ig = ibase + r;
            #pragma unroll
            for (int cc = 0; cc < 4; cc++) {
                const int jg = jbase + cc;
                if (jg > ig) {
                    aout[(size_t)ig * NN + jg] = fmaxf(P[r][cc] - Q[r][cc], 0.0f);
                    aout[(size_t)jg * NN + ig] = fmaxf(Q[r][cc] - P[r][cc], 0.0f);
                } else if (jg == ig) {
                    aout[(size_t)ig * NN + jg] = 0.0f;
                }
            }
        }
    }
}

// ============================================================================
// Kernel 3 (round-9 version, verbatim — FROZEN): per-row top-30, float smem
// list, 256 threads, exact u64 threshold selection.
// ============================================================================
__device__ __forceinline__ u64 shfl64_xor(u64 x, int off) {
    return __shfl_xor_sync(0xffffffffu, x, off);
}

__device__ __forceinline__ void warp_sort64_desc(u64& e0, u64& e1, int lane) {
    #pragma unroll
    for (int size = 2; size <= 64; size <<= 1) {
        #pragma unroll
        for (int stride = size >> 1; stride > 0; stride >>= 1) {
            const bool desc = (((2 * lane) & size) == 0);
            if (stride == 1) {
                const u64 lo = (e0 < e1) ? e0 : e1;
                const u64 hi = (e0 < e1) ? e1 : e0;
                e0 = desc ? hi : lo;
                e1 = desc ? lo : hi;
            } else {
                const int half = stride >> 1;
                const u64 p0 = shfl64_xor(e0, half);
                const u64 p1 = shfl64_xor(e1, half);
                const bool first = (((2 * lane) & stride) == 0);
                const bool keepmax = (first == desc);
                e0 = keepmax ? (e0 > p0 ? e0 : p0) : (e0 < p0 ? e0 : p0);
                e1 = keepmax ? (e1 > p1 ? e1 : p1) : (e1 < p1 ? e1 : p1);
            }
        }
    }
}

__global__ void __launch_bounds__(256) topk_kernel(float* __restrict__ out,
                                                   long long abase,
                                                   int write_edges)
{
    __shared__ float vlist[8][1024];      // 32 KB
    __shared__ u64 cand[8][64];           // 4 KB
    __shared__ u64 wtop[8][TOPK];
    __shared__ u64 topkeys[TOPK];

    const int row = blockIdx.x;
    const int tid = threadIdx.x;
    const int lane = tid & 31;
    const int w = tid >> 5;
    float* arow = out + abase + (size_t)row * NN;

    u64 m1 = 0ULL, m2 = 0ULL;
    const float4 z4 = make_float4(0.f, 0.f, 0.f, 0.f);
    #pragma unroll
    for (int q = 0; q < 8; q++) {
        const int base = (tid + 256 * q) * 4;
        float4 t = *(const float4*)&arow[base];
        *(float4*)&arow[base] = z4;
        const float vv[4] = { t.x, t.y, t.z, t.w };
        #pragma unroll
        for (int c = 0; c < 4; c++) {
            vlist[w][(q * 4 + c) * 32 + lane] = vv[c];
            const u64 key = ((u64)__float_as_uint(vv[c]) << 13) | (u64)(8191 - (base + c));
            const bool g = key > m1;
            const u64 nm2 = g ? m1 : ((key > m2) ? key : m2);
            m1 = g ? key : m1;
            m2 = nm2;
        }
    }

    warp_sort64_desc(m1, m2, lane);
    const u64 T = __shfl_sync(0xffffffffu, m2, 14);   // rank-29

    cand[w][2 * lane] = 0ULL;
    cand[w][2 * lane + 1] = 0ULL;
    __syncwarp();

    int cnt = 0;
    const unsigned lml = (1u << lane) - 1u;
    #pragma unroll
    for (int i = 0; i < 32; i++) {
        const float v = vlist[w][i * 32 + lane];
        const int col = 128 * w + 1024 * (i >> 2) + 4 * lane + (i & 3);
        const u64 key = ((u64)__float_as_uint(v) << 13) | (u64)(8191 - col);
        const bool p = (key >= T);
        const unsigned msk = __ballot_sync(0xffffffffu, p);
        if (p) {
            const int pos = cnt + __popc(msk & lml);
            if (pos < 64) cand[w][pos] = key;
        }
        cnt += __popc(msk);
    }
    __syncwarp();

    if (cnt <= 64) {
        u64 t0 = cand[w][2 * lane];
        u64 t1 = cand[w][2 * lane + 1];
        warp_sort64_desc(t0, t1, lane);
        if (lane < 15) {
            wtop[w][2 * lane] = t0;
            wtop[w][2 * lane + 1] = t1;
        }
    } else {
        unsigned taken = 0u;
        for (int it = 0; it < TOPK; it++) {
            u64 best = 0ULL;
            int besti = 0;
            #pragma unroll
            for (int i = 0; i < 32; i++) {
                if (!(taken & (1u << i))) {
                    const float v = vlist[w][i * 32 + lane];
                    const int col = 128 * w + 1024 * (i >> 2) + 4 * lane + (i & 3);
                    const u64 key = ((u64)__float_as_uint(v) << 13) | (u64)(8191 - col);
                    if (key > best) { best = key; besti = i; }
                }
            }
            u64 m = best;
            #pragma unroll
            for (int off = 16; off; off >>= 1) {
                const u64 om = shfl64_xor(m, off);
                if (om > m) m = om;
            }
            if (lane == 0) wtop[w][it] = m;
            if (best == m) taken |= (1u << besti);
        }
    }
    __syncthreads();

    if (w == 0) {
        int h = 0;
        u64 head = (lane < 8) ? wtop[lane][0] : 0ULL;
        for (int it = 0; it < TOPK; it++) {
            u64 m = head;
            #pragma unroll
            for (int off = 4; off; off >>= 1) {
                const u64 om = shfl64_xor(m, off);
                if (om > m) m = om;
            }
            if (lane == 0) topkeys[it] = m;
            if (lane < 8 && head == m) {
                h++;
                head = (h < TOPK) ? wtop[lane][h] : 0ULL;
            }
        }
    }
    __syncthreads();

    if (tid < TOPK) {
        const u64 key = topkeys[tid];
        const float val = __uint_as_float((unsigned)(key >> 13));
        const int dst = 8191 - (int)(key & 8191);
        arow[dst] = val;
        if (write_edges) {
            const long long e = (long long)row * TOPK + tid;
            out[e] = (float)row;                                // src
            out[(long long)NN * TOPK + e] = (float)dst;         // dst
            out[2LL * NN * TOPK + e] = val;                     // attr
        }
    }
}

// ============================================================================
// launch
// ============================================================================
extern "C" void kernel_launch(void* const* d_in, const int* in_sizes, int n_in,
                              void* d_out, int out_size)
{
    const float* E1 = (const float*)d_in[0];
    const float* E2 = (const float*)d_in[1];
    const float* W1 = (const float*)d_in[2];
    const float* b1 = (const float*)d_in[3];
    const float* W2 = (const float*)d_in[4];
    const float* b2 = (const float*)d_in[5];
    float* out = (float*)d_out;

    cudaFuncSetAttribute(prep_kernel, cudaFuncAttributeMaxDynamicSharedMemorySize, 81920);
    cudaFuncSetAttribute(gemm_kernel, cudaFuncAttributeMaxDynamicSharedMemorySize, 98304);

    long long abase;
    int write_edges;
    if (out_size == (long long)NN * NN) { abase = 0; write_edges = 0; }
    else { abase = 3LL * NN * TOPK; write_edges = 1; }

    prep_kernel<<<dim3(NN / 32, 2), 256, 81920>>>(E1, W1, b1, E2, W2, b2);
    gemm_kernel<<<dim3(128, 64), 256, 98304>>>(out + abase);
    topk_kernel<<<NN, 256>>>(out, abase, write_edges);
}

// round 16
// speedup vs baseline: 1.1878x; 1.0422x over previous
#include <cuda_runtime.h>
#include <math.h>
#include <float.h>
#include <stdint.h>

#define NN 8192
#define DD 128
#define TOPK 30

typedef unsigned long long u64;

// ---- scratch (device globals; no runtime allocation allowed) ----
__device__ float g_M1t[DD * NN];              // M1^T  [128][8192]
__device__ float g_M2t[DD * NN];              // M2^T  [128][8192]

// ============================================================================
// packed f32x2 helpers (Blackwell sm_103a): 2 IEEE fp32 FMAs per issue slot.
// ============================================================================
__device__ __forceinline__ void fma2(u64& d, u64 a, u64 b) {
    asm("fma.rn.f32x2 %0, %1, %2, %0;" : "+l"(d) : "l"(a), "l"(b));
}
__device__ __forceinline__ u64 pack2(float x) {
    u64 r; asm("mov.b64 %0, {%1, %1};" : "=l"(r) : "f"(x)); return r;
}
__device__ __forceinline__ float2 unpk(u64 x) {
    float2 f; asm("mov.b64 {%0, %1}, %2;" : "=f"(f.x), "=f"(f.y) : "l"(x)); return f;
}

// ============================================================================
// XLA/Eigen f32 tanh replica (EmitTanh / generic_fast_tanh_float).
// ============================================================================
__device__ __forceinline__ float xla_tanh(float x) {
    const float kClamp = 7.90531110763549805f;
    const bool tiny = fabsf(x) < 0.0004f;
    float xc = fminf(fmaxf(x, -kClamp), kClamp);
    float x2 = xc * xc;
    float p = fmaf(x2, -2.76076847742355e-16f, 2.00018790482477e-13f);
    p = fmaf(x2, p, -8.60467152213735e-11f);
    p = fmaf(x2, p, 5.12229709037114e-08f);
    p = fmaf(x2, p, 1.48572235717979e-05f);
    p = fmaf(x2, p, 6.37261928875436e-04f);
    p = fmaf(x2, p, 4.89352455891786e-03f);
    p = xc * p;
    float q = fmaf(x2, 1.19825839466702e-06f, 1.18534705686654e-04f);
    q = fmaf(x2, q, 2.26843463243900e-03f);
    q = fmaf(x2, q, 4.89352518554385e-03f);
    float r = __fdiv_rn(p, q);
    return tiny ? x : r;
}

// ============================================================================
// Kernel 1 (round-9, unchanged): M = tanh(3*(E @ W^T + b)); transposed store.
// ============================================================================
__global__ void prep_kernel(const float* __restrict__ E1,
                            const float* __restrict__ W1,
                            const float* __restrict__ b1,
                            const float* __restrict__ E2,
                            const float* __restrict__ W2,
                            const float* __restrict__ b2)
{
    extern __shared__ float sh[];
    float* Ws = sh;               // 128 rows x 128 (swizzled)
    float* Es = sh + DD * DD;     // 32 rows x 128 (swizzled)
    __shared__ float bs[DD];

    const int mode = blockIdx.y;
    const float* __restrict__ E = mode ? E2 : E1;
    const float* __restrict__ W = mode ? W2 : W1;
    const float* __restrict__ b = mode ? b2 : b1;
    float* __restrict__ Mt = mode ? g_M2t : g_M1t;

    const int tid = threadIdx.x;
    const int row0 = blockIdx.x * 32;

    {
        const float4* W4 = (const float4*)W;
        #pragma unroll 4
        for (int i = tid; i < DD * DD / 4; i += 256) {
            const int rowm = i >> 5, q = i & 31;
            float4 v = W4[i];
            *(float4*)&Ws[rowm * DD + ((4 * q + 4 * (rowm >> 2)) & 127)] = v;
        }
        const float4* E4 = (const float4*)(E + (size_t)row0 * DD);
        #pragma unroll
        for (int i = tid; i < 32 * DD / 4; i += 256) {
            const int rowm = i >> 5, q = i & 31;
            float4 v = E4[i];
            *(float4*)&Es[rowm * DD + ((4 * q + 4 * (rowm >> 2)) & 127)] = v;
        }
        if (tid < DD) bs[tid] = b[tid];
    }
    __syncthreads();

    const int tx = tid & 7;
    const int ty = tid >> 3;

    float acc[4][4];
    #pragma unroll
    for (int r = 0; r < 4; r++)
        #pragma unroll
        for (int c = 0; c < 4; c++) acc[r][c] = 0.0f;

    #pragma unroll 8
    for (int k = 0; k < DD; k += 4) {
        const int ke = (k + 4 * tx) & 127;
        const int kw = (k + 4 * ty) & 127;
        float4 ev[4], wv[4];
        #pragma unroll
        for (int r = 0; r < 4; r++) ev[r] = *(const float4*)&Es[(tx * 4 + r) * DD + ke];
        #pragma unroll
        for (int c = 0; c < 4; c++) wv[c] = *(const float4*)&Ws[(ty * 4 + c) * DD + kw];
        #pragma unroll
        for (int r = 0; r < 4; r++)
            #pragma unroll
            for (int c = 0; c < 4; c++) {
                acc[r][c] = fmaf(ev[r].x, wv[c].x, acc[r][c]);
                acc[r][c] = fmaf(ev[r].y, wv[c].y, acc[r][c]);
                acc[r][c] = fmaf(ev[r].z, wv[c].z, acc[r][c]);
                acc[r][c] = fmaf(ev[r].w, wv[c].w, acc[r][c]);
            }
    }

    #pragma unroll
    for (int c = 0; c < 4; c++) {
        const int d = ty * 4 + c;
        float m[4];
        #pragma unroll
        for (int r = 0; r < 4; r++) {
            const float t = acc[r][c] + bs[d];
            const float u = 3.0f * t;
            m[r] = xla_tanh(u);
        }
        const int rowb = row0 + tx * 4;
        float4 v; v.x = m[0]; v.y = m[1]; v.z = m[2]; v.w = m[3];
        *(float4*)&Mt[(size_t)d * NN + rowb] = v;
    }
}

// ============================================================================
// Kernel 2 (round-15 body; single change: cp.async.cg — L1 bypass for tile
// loads). 128x64 tile, BK=32, 2 CTAs/SM, row-paired f32x2 FMA chains,
// bit-exact ascending-k. bj >= 2*bi tiles only. dyn smem = 98304 B.
// ============================================================================
#define BK 32
#define NCHUNK (DD / BK)          // 4
#define ARR_I (BK * 128)          // 4096 floats
#define ARR_J (BK * 64)           // 2048 floats
#define BUF (2 * ARR_I + 2 * ARR_J)   // 12288 floats per buffer

__device__ __forceinline__ void cp16(uint32_t smem_dst, const float* gsrc) {
    asm volatile("cp.async.cg.shared.global [%0], [%1], 16;\n"
                 :: "r"(smem_dst), "l"(gsrc));
}

__global__ void __launch_bounds__(256, 2) gemm_kernel(float* __restrict__ aout)
{
    const int bi = blockIdx.y;
    const int bj = blockIdx.x;
    if (bj < 2 * bi) return;

    extern __shared__ float sh[];

    const int I0 = bi * 128, J0 = bj * 64;
    const int tid = threadIdx.x;
    const int tx = tid & 15;
    const int ty = tid >> 4;

    const uint32_t sbase = (uint32_t)__cvta_generic_to_shared(sh);

    auto issue_chunk = [&](int c, int buf) {
        const int kb = c * BK;
        // I-side: 2 arrays x 32 kk x 32 quads = 2048 float4 (8 per thread)
        #pragma unroll
        for (int j = 0; j < 8; j++) {
            const int f = tid + 256 * j;
            const int arr = f >> 10;
            const int idx = f & 1023;
            const int kk = idx >> 5, q = idx & 31;
            const float* src = (arr ? g_M2t : g_M1t) + (size_t)(kb + kk) * NN + I0 + q * 4;
            cp16(sbase + (uint32_t)((buf * BUF + arr * ARR_I + kk * 128 + q * 4) * 4), src);
        }
        // J-side: 2 arrays x 32 kk x 16 quads = 1024 float4 (4 per thread)
        #pragma unroll
        for (int j = 0; j < 4; j++) {
            const int f = tid + 256 * j;
            const int arr = f >> 9;
            const int idx = f & 511;
            const int kk = idx >> 4, q = idx & 15;
            const float* src = (arr ? g_M2t : g_M1t) + (size_t)(kb + kk) * NN + J0 + q * 4;
            cp16(sbase + (uint32_t)((buf * BUF + 2 * ARR_I + arr * ARR_J + kk * 64 + q * 4) * 4), src);
        }
        asm volatile("cp.async.commit_group;\n");
    };

    issue_chunk(0, 0);

    u64 accP[4][4], accQ[4][4];
    #pragma unroll
    for (int r = 0; r < 4; r++)
        #pragma unroll
        for (int c = 0; c < 4; c++) { accP[r][c] = 0ULL; accQ[r][c] = 0ULL; }

    for (int c = 0; c < NCHUNK; c++) {
        const int cur = c & 1;
        if (c < NCHUNK - 1) {
            issue_chunk(c + 1, cur ^ 1);
            asm volatile("cp.async.wait_group 1;\n");
        } else {
            asm volatile("cp.async.wait_group 0;\n");
        }
        __syncthreads();

        const float* M1I = sh + cur * BUF;
        const float* M2I = sh + cur * BUF + ARR_I;
        const float* M1J = sh + cur * BUF + 2 * ARR_I;
        const float* M2J = sh + cur * BUF + 2 * ARR_I + ARR_J;

        #pragma unroll
        for (int kk = 0; kk < BK; kk++) {
            ulonglong2 a1lo = *(const ulonglong2*)&M1I[kk * 128 + ty * 8];
            ulonglong2 a1hi = *(const ulonglong2*)&M1I[kk * 128 + ty * 8 + 4];
            ulonglong2 a2lo = *(const ulonglong2*)&M2I[kk * 128 + ty * 8];
            ulonglong2 a2hi = *(const ulonglong2*)&M2I[kk * 128 + ty * 8 + 4];
            u64 a1p[4] = { a1lo.x, a1lo.y, a1hi.x, a1hi.y };
            u64 a2p[4] = { a2lo.x, a2lo.y, a2hi.x, a2hi.y };
            float4 f1 = *(const float4*)&M1J[kk * 64 + tx * 4];
            float4 f2 = *(const float4*)&M2J[kk * 64 + tx * 4];
            u64 b1d[4] = { pack2(f1.x), pack2(f1.y), pack2(f1.z), pack2(f1.w) };
            u64 b2d[4] = { pack2(f2.x), pack2(f2.y), pack2(f2.z), pack2(f2.w) };
            #pragma unroll
            for (int rp = 0; rp < 4; rp++)
                #pragma unroll
                for (int cc = 0; cc < 4; cc++) {
                    fma2(accP[rp][cc], a1p[rp], b2d[cc]);
                    fma2(accQ[rp][cc], a2p[rp], b1d[cc]);
                }
        }
        __syncthreads();
    }

    float P[8][4], Q[8][4];
    #pragma unroll
    for (int rp = 0; rp < 4; rp++)
        #pragma unroll
        for (int cc = 0; cc < 4; cc++) {
            float2 fp = unpk(accP[rp][cc]);
            float2 fq = unpk(accQ[rp][cc]);
            P[2*rp][cc] = fp.x; P[2*rp+1][cc] = fp.y;
            Q[2*rp][cc] = fq.x; Q[2*rp+1][cc] = fq.y;
        }

    const int ibase = I0 + ty * 8;
    const int jbase = J0 + tx * 4;
    const bool cross = ((bj >> 1) == bi);

    if (!cross) {
        #pragma unroll
        for (int r = 0; r < 8; r++) {
            float4 w;
            w.x = fmaxf(P[r][0] - Q[r][0], 0.0f);
            w.y = fmaxf(P[r][1] - Q[r][1], 0.0f);
            w.z = fmaxf(P[r][2] - Q[r][2], 0.0f);
            w.w = fmaxf(P[r][3] - Q[r][3], 0.0f);
            *(float4*)&aout[(size_t)(ibase + r) * NN + jbase] = w;
        }
        #pragma unroll
        for (int cc = 0; cc < 4; cc++) {
            const int jg = jbase + cc;
            float4 w0, w1;
            w0.x = fmaxf(Q[0][cc] - P[0][cc], 0.0f);
            w0.y = fmaxf(Q[1][cc] - P[1][cc], 0.0f);
            w0.z = fmaxf(Q[2][cc] - P[2][cc], 0.0f);
            w0.w = fmaxf(Q[3][cc] - P[3][cc], 0.0f);
            w1.x = fmaxf(Q[4][cc] - P[4][cc], 0.0f);
            w1.y = fmaxf(Q[5][cc] - P[5][cc], 0.0f);
            w1.z = fmaxf(Q[6][cc] - P[6][cc], 0.0f);
            w1.w = fmaxf(Q[7][cc] - P[7][cc], 0.0f);
            *(float4*)&aout[(size_t)jg * NN + ibase] = w0;
            *(float4*)&aout[(size_t)jg * NN + ibase + 4] = w1;
        }
    } else {
        #pragma unroll
        for (int r = 0; r < 8; r++) {
            const int ig = ibase + r;
            #pragma unroll
            for (int cc = 0; cc < 4; cc++) {
                const int jg = jbase + cc;
                if (jg > ig) {
                    aout[(size_t)ig * NN + jg] = fmaxf(P[r][cc] - Q[r][cc], 0.0f);
                    aout[(size_t)jg * NN + ig] = fmaxf(Q[r][cc] - P[r][cc], 0.0f);
                } else if (jg == ig) {
                    aout[(size_t)ig * NN + jg] = 0.0f;
                }
            }
        }
    }
}

// ============================================================================
// Kernel 3 (round-9 version, verbatim — FROZEN): per-row top-30, float smem
// list, 256 threads, exact u64 threshold selection.
// ============================================================================
__device__ __forceinline__ u64 shfl64_xor(u64 x, int off) {
    return __shfl_xor_sync(0xffffffffu, x, off);
}

__device__ __forceinline__ void warp_sort64_desc(u64& e0, u64& e1, int lane) {
    #pragma unroll
    for (int size = 2; size <= 64; size <<= 1) {
        #pragma unroll
        for (int stride = size >> 1; stride > 0; stride >>= 1) {
            const bool desc = (((2 * lane) & size) == 0);
            if (stride == 1) {
                const u64 lo = (e0 < e1) ? e0 : e1;
                const u64 hi = (e0 < e1) ? e1 : e0;
                e0 = desc ? hi : lo;
                e1 = desc ? lo : hi;
            } else {
                const int half = stride >> 1;
                const u64 p0 = shfl64_xor(e0, half);
                const u64 p1 = shfl64_xor(e1, half);
                const bool first = (((2 * lane) & stride) == 0);
                const bool keepmax = (first == desc);
                e0 = keepmax ? (e0 > p0 ? e0 : p0) : (e0 < p0 ? e0 : p0);
                e1 = keepmax ? (e1 > p1 ? e1 : p1) : (e1 < p1 ? e1 : p1);
            }
        }
    }
}

__global__ void __launch_bounds__(256) topk_kernel(float* __restrict__ out,
                                                   long long abase,
                                                   int write_edges)
{
    __shared__ float vlist[8][1024];      // 32 KB
    __shared__ u64 cand[8][64];           // 4 KB
    __shared__ u64 wtop[8][TOPK];
    __shared__ u64 topkeys[TOPK];

    const int row = blockIdx.x;
    const int tid = threadIdx.x;
    const int lane = tid & 31;
    const int w = tid >> 5;
    float* arow = out + abase + (size_t)row * NN;

    u64 m1 = 0ULL, m2 = 0ULL;
    const float4 z4 = make_float4(0.f, 0.f, 0.f, 0.f);
    #pragma unroll
    for (int q = 0; q < 8; q++) {
        const int base = (tid + 256 * q) * 4;
        float4 t = *(const float4*)&arow[base];
        *(float4*)&arow[base] = z4;
        const float vv[4] = { t.x, t.y, t.z, t.w };
        #pragma unroll
        for (int c = 0; c < 4; c++) {
            vlist[w][(q * 4 + c) * 32 + lane] = vv[c];
            const u64 key = ((u64)__float_as_uint(vv[c]) << 13) | (u64)(8191 - (base + c));
            const bool g = key > m1;
            const u64 nm2 = g ? m1 : ((key > m2) ? key : m2);
            m1 = g ? key : m1;
            m2 = nm2;
        }
    }

    warp_sort64_desc(m1, m2, lane);
    const u64 T = __shfl_sync(0xffffffffu, m2, 14);   // rank-29

    cand[w][2 * lane] = 0ULL;
    cand[w][2 * lane + 1] = 0ULL;
    __syncwarp();

    int cnt = 0;
    const unsigned lml = (1u << lane) - 1u;
    #pragma unroll
    for (int i = 0; i < 32; i++) {
        const float v = vlist[w][i * 32 + lane];
        const int col = 128 * w + 1024 * (i >> 2) + 4 * lane + (i & 3);
        const u64 key = ((u64)__float_as_uint(v) << 13) | (u64)(8191 - col);
        const bool p = (key >= T);
        const unsigned msk = __ballot_sync(0xffffffffu, p);
        if (p) {
            const int pos = cnt + __popc(msk & lml);
            if (pos < 64) cand[w][pos] = key;
        }
        cnt += __popc(msk);
    }
    __syncwarp();

    if (cnt <= 64) {
        u64 t0 = cand[w][2 * lane];
        u64 t1 = cand[w][2 * lane + 1];
        warp_sort64_desc(t0, t1, lane);
        if (lane < 15) {
            wtop[w][2 * lane] = t0;
            wtop[w][2 * lane + 1] = t1;
        }
    } else {
        unsigned taken = 0u;
        for (int it = 0; it < TOPK; it++) {
            u64 best = 0ULL;
            int besti = 0;
            #pragma unroll
            for (int i = 0; i < 32; i++) {
                if (!(taken & (1u << i))) {
                    const float v = vlist[w][i * 32 + lane];
                    const int col = 128 * w + 1024 * (i >> 2) + 4 * lane + (i & 3);
                    const u64 key = ((u64)__float_as_uint(v) << 13) | (u64)(8191 - col);
                    if (key > best) { best = key; besti = i; }
                }
            }
            u64 m = best;
            #pragma unroll
            for (int off = 16; off; off >>= 1) {
                const u64 om = shfl64_xor(m, off);
                if (om > m) m = om;
            }
            if (lane == 0) wtop[w][it] = m;
            if (best == m) taken |= (1u << besti);
        }
    }
    __syncthreads();

    if (w == 0) {
        int h = 0;
        u64 head = (lane < 8) ? wtop[lane][0] : 0ULL;
        for (int it = 0; it < TOPK; it++) {
            u64 m = head;
            #pragma unroll
            for (int off = 4; off; off >>= 1) {
                const u64 om = shfl64_xor(m, off);
                if (om > m) m = om;
            }
            if (lane == 0) topkeys[it] = m;
            if (lane < 8 && head == m) {
                h++;
                head = (h < TOPK) ? wtop[lane][h] : 0ULL;
            }
        }
    }
    __syncthreads();

    if (tid < TOPK) {
        const u64 key = topkeys[tid];
        const float val = __uint_as_float((unsigned)(key >> 13));
        const int dst = 8191 - (int)(key & 8191);
        arow[dst] = val;
        if (write_edges) {
            const long long e = (long long)row * TOPK + tid;
            out[e] = (float)row;                                // src
            out[(long long)NN * TOPK + e] = (float)dst;         // dst
            out[2LL * NN * TOPK + e] = val;                     // attr
        }
    }
}

// ============================================================================
// launch
// ============================================================================
extern "C" void kernel_launch(void* const* d_in, const int* in_sizes, int n_in,
                              void* d_out, int out_size)
{
    const float* E1 = (const float*)d_in[0];
    const float* E2 = (const float*)d_in[1];
    const float* W1 = (const float*)d_in[2];
    const float* b1 = (const float*)d_in[3];
    const float* W2 = (const float*)d_in[4];
    const float* b2 = (const float*)d_in[5];
    float* out = (float*)d_out;

    cudaFuncSetAttribute(prep_kernel, cudaFuncAttributeMaxDynamicSharedMemorySize, 81920);
    cudaFuncSetAttribute(gemm_kernel, cudaFuncAttributeMaxDynamicSharedMemorySize, 98304);

    long long abase;
    int write_edges;
    if (out_size == (long long)NN * NN) { abase = 0; write_edges = 0; }
    else { abase = 3LL * NN * TOPK; write_edges = 1; }

    prep_kernel<<<dim3(NN / 32, 2), 256, 81920>>>(E1, W1, b1, E2, W2, b2);
    gemm_kernel<<<dim3(128, 64), 256, 98304>>>(out + abase);
    topk_kernel<<<NN, 256>>>(out, abase, write_edges);
}

// round 17
// speedup vs baseline: 1.1933x; 1.0046x over previous
#include <cuda_runtime.h>
#include <math.h>
#include <float.h>
#include <stdint.h>

#define NN 8192
#define DD 128
#define TOPK 30

typedef unsigned long long u64;

// ---- scratch (device globals; no runtime allocation allowed) ----
__device__ float g_M1t[DD * NN];              // M1^T  [128][8192]
__device__ float g_M2t[DD * NN];              // M2^T  [128][8192]

// ============================================================================
// packed f32x2 helpers (Blackwell sm_103a): 2 IEEE fp32 FMAs per issue slot.
// ============================================================================
__device__ __forceinline__ void fma2(u64& d, u64 a, u64 b) {
    asm("fma.rn.f32x2 %0, %1, %2, %0;" : "+l"(d) : "l"(a), "l"(b));
}
__device__ __forceinline__ u64 pack2(float x) {
    u64 r; asm("mov.b64 %0, {%1, %1};" : "=l"(r) : "f"(x)); return r;
}
__device__ __forceinline__ float2 unpk(u64 x) {
    float2 f; asm("mov.b64 {%0, %1}, %2;" : "=f"(f.x), "=f"(f.y) : "l"(x)); return f;
}
// streaming (evict-first) stores: keep the 256MB A stream from displacing the
// L2-resident M operand arrays.
__device__ __forceinline__ void stg_cs4(float* p, float4 v) {
    asm volatile("st.global.cs.v4.f32 [%0], {%1, %2, %3, %4};"
                 :: "l"(p), "f"(v.x), "f"(v.y), "f"(v.z), "f"(v.w) : "memory");
}
__device__ __forceinline__ void stg_cs1(float* p, float v) {
    asm volatile("st.global.cs.f32 [%0], %1;" :: "l"(p), "f"(v) : "memory");
}

// ============================================================================
// XLA/Eigen f32 tanh replica (EmitTanh / generic_fast_tanh_float).
// ============================================================================
__device__ __forceinline__ float xla_tanh(float x) {
    const float kClamp = 7.90531110763549805f;
    const bool tiny = fabsf(x) < 0.0004f;
    float xc = fminf(fmaxf(x, -kClamp), kClamp);
    float x2 = xc * xc;
    float p = fmaf(x2, -2.76076847742355e-16f, 2.00018790482477e-13f);
    p = fmaf(x2, p, -8.60467152213735e-11f);
    p = fmaf(x2, p, 5.12229709037114e-08f);
    p = fmaf(x2, p, 1.48572235717979e-05f);
    p = fmaf(x2, p, 6.37261928875436e-04f);
    p = fmaf(x2, p, 4.89352455891786e-03f);
    p = xc * p;
    float q = fmaf(x2, 1.19825839466702e-06f, 1.18534705686654e-04f);
    q = fmaf(x2, q, 2.26843463243900e-03f);
    q = fmaf(x2, q, 4.89352518554385e-03f);
    float r = __fdiv_rn(p, q);
    return tiny ? x : r;
}

// ============================================================================
// Kernel 1 (round-9, unchanged): M = tanh(3*(E @ W^T + b)); transposed store.
// ============================================================================
__global__ void prep_kernel(const float* __restrict__ E1,
                            const float* __restrict__ W1,
                            const float* __restrict__ b1,
                            const float* __restrict__ E2,
                            const float* __restrict__ W2,
                            const float* __restrict__ b2)
{
    extern __shared__ float sh[];
    float* Ws = sh;               // 128 rows x 128 (swizzled)
    float* Es = sh + DD * DD;     // 32 rows x 128 (swizzled)
    __shared__ float bs[DD];

    const int mode = blockIdx.y;
    const float* __restrict__ E = mode ? E2 : E1;
    const float* __restrict__ W = mode ? W2 : W1;
    const float* __restrict__ b = mode ? b2 : b1;
    float* __restrict__ Mt = mode ? g_M2t : g_M1t;

    const int tid = threadIdx.x;
    const int row0 = blockIdx.x * 32;

    {
        const float4* W4 = (const float4*)W;
        #pragma unroll 4
        for (int i = tid; i < DD * DD / 4; i += 256) {
            const int rowm = i >> 5, q = i & 31;
            float4 v = W4[i];
            *(float4*)&Ws[rowm * DD + ((4 * q + 4 * (rowm >> 2)) & 127)] = v;
        }
        const float4* E4 = (const float4*)(E + (size_t)row0 * DD);
        #pragma unroll
        for (int i = tid; i < 32 * DD / 4; i += 256) {
            const int rowm = i >> 5, q = i & 31;
            float4 v = E4[i];
            *(float4*)&Es[rowm * DD + ((4 * q + 4 * (rowm >> 2)) & 127)] = v;
        }
        if (tid < DD) bs[tid] = b[tid];
    }
    __syncthreads();

    const int tx = tid & 7;
    const int ty = tid >> 3;

    float acc[4][4];
    #pragma unroll
    for (int r = 0; r < 4; r++)
        #pragma unroll
        for (int c = 0; c < 4; c++) acc[r][c] = 0.0f;

    #pragma unroll 8
    for (int k = 0; k < DD; k += 4) {
        const int ke = (k + 4 * tx) & 127;
        const int kw = (k + 4 * ty) & 127;
        float4 ev[4], wv[4];
        #pragma unroll
        for (int r = 0; r < 4; r++) ev[r] = *(const float4*)&Es[(tx * 4 + r) * DD + ke];
        #pragma unroll
        for (int c = 0; c < 4; c++) wv[c] = *(const float4*)&Ws[(ty * 4 + c) * DD + kw];
        #pragma unroll
        for (int r = 0; r < 4; r++)
            #pragma unroll
            for (int c = 0; c < 4; c++) {
                acc[r][c] = fmaf(ev[r].x, wv[c].x, acc[r][c]);
                acc[r][c] = fmaf(ev[r].y, wv[c].y, acc[r][c]);
                acc[r][c] = fmaf(ev[r].z, wv[c].z, acc[r][c]);
                acc[r][c] = fmaf(ev[r].w, wv[c].w, acc[r][c]);
            }
    }

    #pragma unroll
    for (int c = 0; c < 4; c++) {
        const int d = ty * 4 + c;
        float m[4];
        #pragma unroll
        for (int r = 0; r < 4; r++) {
            const float t = acc[r][c] + bs[d];
            const float u = 3.0f * t;
            m[r] = xla_tanh(u);
        }
        const int rowb = row0 + tx * 4;
        float4 v; v.x = m[0]; v.y = m[1]; v.z = m[2]; v.w = m[3];
        *(float4*)&Mt[(size_t)d * NN + rowb] = v;
    }
}

// ============================================================================
// Kernel 2 (round-16 body; single change: epilogue stores use st.global.cs
// (evict-first) to protect L2-resident M operands from the 256MB A stream).
// 128x64 tile, BK=32, 2 CTAs/SM, cp.async.cg loads, row-paired f32x2 FMA
// chains, bit-exact ascending-k. bj >= 2*bi tiles only. dyn smem = 98304 B.
// ============================================================================
#define BK 32
#define NCHUNK (DD / BK)          // 4
#define ARR_I (BK * 128)          // 4096 floats
#define ARR_J (BK * 64)           // 2048 floats
#define BUF (2 * ARR_I + 2 * ARR_J)   // 12288 floats per buffer

__device__ __forceinline__ void cp16(uint32_t smem_dst, const float* gsrc) {
    asm volatile("cp.async.cg.shared.global [%0], [%1], 16;\n"
                 :: "r"(smem_dst), "l"(gsrc));
}

__global__ void __launch_bounds__(256, 2) gemm_kernel(float* __restrict__ aout)
{
    const int bi = blockIdx.y;
    const int bj = blockIdx.x;
    if (bj < 2 * bi) return;

    extern __shared__ float sh[];

    const int I0 = bi * 128, J0 = bj * 64;
    const int tid = threadIdx.x;
    const int tx = tid & 15;
    const int ty = tid >> 4;

    const uint32_t sbase = (uint32_t)__cvta_generic_to_shared(sh);

    auto issue_chunk = [&](int c, int buf) {
        const int kb = c * BK;
        #pragma unroll
        for (int j = 0; j < 8; j++) {
            const int f = tid + 256 * j;
            const int arr = f >> 10;
            const int idx = f & 1023;
            const int kk = idx >> 5, q = idx & 31;
            const float* src = (arr ? g_M2t : g_M1t) + (size_t)(kb + kk) * NN + I0 + q * 4;
            cp16(sbase + (uint32_t)((buf * BUF + arr * ARR_I + kk * 128 + q * 4) * 4), src);
        }
        #pragma unroll
        for (int j = 0; j < 4; j++) {
            const int f = tid + 256 * j;
            const int arr = f >> 9;
            const int idx = f & 511;
            const int kk = idx >> 4, q = idx & 15;
            const float* src = (arr ? g_M2t : g_M1t) + (size_t)(kb + kk) * NN + J0 + q * 4;
            cp16(sbase + (uint32_t)((buf * BUF + 2 * ARR_I + arr * ARR_J + kk * 64 + q * 4) * 4), src);
        }
        asm volatile("cp.async.commit_group;\n");
    };

    issue_chunk(0, 0);

    u64 accP[4][4], accQ[4][4];
    #pragma unroll
    for (int r = 0; r < 4; r++)
        #pragma unroll
        for (int c = 0; c < 4; c++) { accP[r][c] = 0ULL; accQ[r][c] = 0ULL; }

    for (int c = 0; c < NCHUNK; c++) {
        const int cur = c & 1;
        if (c < NCHUNK - 1) {
            issue_chunk(c + 1, cur ^ 1);
            asm volatile("cp.async.wait_group 1;\n");
        } else {
            asm volatile("cp.async.wait_group 0;\n");
        }
        __syncthreads();

        const float* M1I = sh + cur * BUF;
        const float* M2I = sh + cur * BUF + ARR_I;
        const float* M1J = sh + cur * BUF + 2 * ARR_I;
        const float* M2J = sh + cur * BUF + 2 * ARR_I + ARR_J;

        #pragma unroll
        for (int kk = 0; kk < BK; kk++) {
            ulonglong2 a1lo = *(const ulonglong2*)&M1I[kk * 128 + ty * 8];
            ulonglong2 a1hi = *(const ulonglong2*)&M1I[kk * 128 + ty * 8 + 4];
            ulonglong2 a2lo = *(const ulonglong2*)&M2I[kk * 128 + ty * 8];
            ulonglong2 a2hi = *(const ulonglong2*)&M2I[kk * 128 + ty * 8 + 4];
            u64 a1p[4] = { a1lo.x, a1lo.y, a1hi.x, a1hi.y };
            u64 a2p[4] = { a2lo.x, a2lo.y, a2hi.x, a2hi.y };
            float4 f1 = *(const float4*)&M1J[kk * 64 + tx * 4];
            float4 f2 = *(const float4*)&M2J[kk * 64 + tx * 4];
            u64 b1d[4] = { pack2(f1.x), pack2(f1.y), pack2(f1.z), pack2(f1.w) };
            u64 b2d[4] = { pack2(f2.x), pack2(f2.y), pack2(f2.z), pack2(f2.w) };
            #pragma unroll
            for (int rp = 0; rp < 4; rp++)
                #pragma unroll
                for (int cc = 0; cc < 4; cc++) {
                    fma2(accP[rp][cc], a1p[rp], b2d[cc]);
                    fma2(accQ[rp][cc], a2p[rp], b1d[cc]);
                }
        }
        __syncthreads();
    }

    float P[8][4], Q[8][4];
    #pragma unroll
    for (int rp = 0; rp < 4; rp++)
        #pragma unroll
        for (int cc = 0; cc < 4; cc++) {
            float2 fp = unpk(accP[rp][cc]);
            float2 fq = unpk(accQ[rp][cc]);
            P[2*rp][cc] = fp.x; P[2*rp+1][cc] = fp.y;
            Q[2*rp][cc] = fq.x; Q[2*rp+1][cc] = fq.y;
        }

    const int ibase = I0 + ty * 8;
    const int jbase = J0 + tx * 4;
    const bool cross = ((bj >> 1) == bi);

    if (!cross) {
        #pragma unroll
        for (int r = 0; r < 8; r++) {
            float4 w;
            w.x = fmaxf(P[r][0] - Q[r][0], 0.0f);
            w.y = fmaxf(P[r][1] - Q[r][1], 0.0f);
            w.z = fmaxf(P[r][2] - Q[r][2], 0.0f);
            w.w = fmaxf(P[r][3] - Q[r][3], 0.0f);
            stg_cs4(&aout[(size_t)(ibase + r) * NN + jbase], w);
        }
        #pragma unroll
        for (int cc = 0; cc < 4; cc++) {
            const int jg = jbase + cc;
            float4 w0, w1;
            w0.x = fmaxf(Q[0][cc] - P[0][cc], 0.0f);
            w0.y = fmaxf(Q[1][cc] - P[1][cc], 0.0f);
            w0.z = fmaxf(Q[2][cc] - P[2][cc], 0.0f);
            w0.w = fmaxf(Q[3][cc] - P[3][cc], 0.0f);
            w1.x = fmaxf(Q[4][cc] - P[4][cc], 0.0f);
            w1.y = fmaxf(Q[5][cc] - P[5][cc], 0.0f);
            w1.z = fmaxf(Q[6][cc] - P[6][cc], 0.0f);
            w1.w = fmaxf(Q[7][cc] - P[7][cc], 0.0f);
            stg_cs4(&aout[(size_t)jg * NN + ibase], w0);
            stg_cs4(&aout[(size_t)jg * NN + ibase + 4], w1);
        }
    } else {
        #pragma unroll
        for (int r = 0; r < 8; r++) {
            const int ig = ibase + r;
            #pragma unroll
            for (int cc = 0; cc < 4; cc++) {
                const int jg = jbase + cc;
                if (jg > ig) {
                    stg_cs1(&aout[(size_t)ig * NN + jg], fmaxf(P[r][cc] - Q[r][cc], 0.0f));
                    stg_cs1(&aout[(size_t)jg * NN + ig], fmaxf(Q[r][cc] - P[r][cc], 0.0f));
                } else if (jg == ig) {
                    stg_cs1(&aout[(size_t)ig * NN + jg], 0.0f);
                }
            }
        }
    }
}

// ============================================================================
// Kernel 3 (round-9 version, verbatim — FROZEN): per-row top-30, float smem
// list, 256 threads, exact u64 threshold selection.
// ============================================================================
__device__ __forceinline__ u64 shfl64_xor(u64 x, int off) {
    return __shfl_xor_sync(0xffffffffu, x, off);
}

__device__ __forceinline__ void warp_sort64_desc(u64& e0, u64& e1, int lane) {
    #pragma unroll
    for (int size = 2; size <= 64; size <<= 1) {
        #pragma unroll
        for (int stride = size >> 1; stride > 0; stride >>= 1) {
            const bool desc = (((2 * lane) & size) == 0);
            if (stride == 1) {
                const u64 lo = (e0 < e1) ? e0 : e1;
                const u64 hi = (e0 < e1) ? e1 : e0;
                e0 = desc ? hi : lo;
                e1 = desc ? lo : hi;
            } else {
                const int half = stride >> 1;
                const u64 p0 = shfl64_xor(e0, half);
                const u64 p1 = shfl64_xor(e1, half);
                const bool first = (((2 * lane) & stride) == 0);
                const bool keepmax = (first == desc);
                e0 = keepmax ? (e0 > p0 ? e0 : p0) : (e0 < p0 ? e0 : p0);
                e1 = keepmax ? (e1 > p1 ? e1 : p1) : (e1 < p1 ? e1 : p1);
            }
        }
    }
}

__global__ void __launch_bounds__(256) topk_kernel(float* __restrict__ out,
                                                   long long abase,
                                                   int write_edges)
{
    __shared__ float vlist[8][1024];      // 32 KB
    __shared__ u64 cand[8][64];           // 4 KB
    __shared__ u64 wtop[8][TOPK];
    __shared__ u64 topkeys[TOPK];

    const int row = blockIdx.x;
    const int tid = threadIdx.x;
    const int lane = tid & 31;
    const int w = tid >> 5;
    float* arow = out + abase + (size_t)row * NN;

    u64 m1 = 0ULL, m2 = 0ULL;
    const float4 z4 = make_float4(0.f, 0.f, 0.f, 0.f);
    #pragma unroll
    for (int q = 0; q < 8; q++) {
        const int base = (tid + 256 * q) * 4;
        float4 t = *(const float4*)&arow[base];
        *(float4*)&arow[base] = z4;
        const float vv[4] = { t.x, t.y, t.z, t.w };
        #pragma unroll
        for (int c = 0; c < 4; c++) {
            vlist[w][(q * 4 + c) * 32 + lane] = vv[c];
            const u64 key = ((u64)__float_as_uint(vv[c]) << 13) | (u64)(8191 - (base + c));
            const bool g = key > m1;
            const u64 nm2 = g ? m1 : ((key > m2) ? key : m2);
            m1 = g ? key : m1;
            m2 = nm2;
        }
    }

    warp_sort64_desc(m1, m2, lane);
    const u64 T = __shfl_sync(0xffffffffu, m2, 14);   // rank-29

    cand[w][2 * lane] = 0ULL;
    cand[w][2 * lane + 1] = 0ULL;
    __syncwarp();

    int cnt = 0;
    const unsigned lml = (1u << lane) - 1u;
    #pragma unroll
    for (int i = 0; i < 32; i++) {
        const float v = vlist[w][i * 32 + lane];
        const int col = 128 * w + 1024 * (i >> 2) + 4 * lane + (i & 3);
        const u64 key = ((u64)__float_as_uint(v) << 13) | (u64)(8191 - col);
        const bool p = (key >= T);
        const unsigned msk = __ballot_sync(0xffffffffu, p);
        if (p) {
            const int pos = cnt + __popc(msk & lml);
            if (pos < 64) cand[w][pos] = key;
        }
        cnt += __popc(msk);
    }
    __syncwarp();

    if (cnt <= 64) {
        u64 t0 = cand[w][2 * lane];
        u64 t1 = cand[w][2 * lane + 1];
        warp_sort64_desc(t0, t1, lane);
        if (lane < 15) {
            wtop[w][2 * lane] = t0;
            wtop[w][2 * lane + 1] = t1;
        }
    } else {
        unsigned taken = 0u;
        for (int it = 0; it < TOPK; it++) {
            u64 best = 0ULL;
            int besti = 0;
            #pragma unroll
            for (int i = 0; i < 32; i++) {
                if (!(taken & (1u << i))) {
                    const float v = vlist[w][i * 32 + lane];
                    const int col = 128 * w + 1024 * (i >> 2) + 4 * lane + (i & 3);
                    const u64 key = ((u64)__float_as_uint(v) << 13) | (u64)(8191 - col);
                    if (key > best) { best = key; besti = i; }
                }
            }
            u64 m = best;
            #pragma unroll
            for (int off = 16; off; off >>= 1) {
                const u64 om = shfl64_xor(m, off);
                if (om > m) m = om;
            }
            if (lane == 0) wtop[w][it] = m;
            if (best == m) taken |= (1u << besti);
        }
    }
    __syncthreads();

    if (w == 0) {
        int h = 0;
        u64 head = (lane < 8) ? wtop[lane][0] : 0ULL;
        for (int it = 0; it < TOPK; it++) {
            u64 m = head;
            #pragma unroll
            for (int off = 4; off; off >>= 1) {
                const u64 om = shfl64_xor(m, off);
                if (om > m) m = om;
            }
            if (lane == 0) topkeys[it] = m;
            if (lane < 8 && head == m) {
                h++;
                head = (h < TOPK) ? wtop[lane][h] : 0ULL;
            }
        }
    }
    __syncthreads();

    if (tid < TOPK) {
        const u64 key = topkeys[tid];
        const float val = __uint_as_float((unsigned)(key >> 13));
        const int dst = 8191 - (int)(key & 8191);
        arow[dst] = val;
        if (write_edges) {
            const long long e = (long long)row * TOPK + tid;
            out[e] = (float)row;                                // src
            out[(long long)NN * TOPK + e] = (float)dst;         // dst
            out[2LL * NN * TOPK + e] = val;                     // attr
        }
    }
}

// ============================================================================
// launch
// ============================================================================
extern "C" void kernel_launch(void* const* d_in, const int* in_sizes, int n_in,
                              void* d_out, int out_size)
{
    const float* E1 = (const float*)d_in[0];
    const float* E2 = (const float*)d_in[1];
    const float* W1 = (const float*)d_in[2];
    const float* b1 = (const float*)d_in[3];
    const float* W2 = (const float*)d_in[4];
    const float* b2 = (const float*)d_in[5];
    float* out = (float*)d_out;

    cudaFuncSetAttribute(prep_kernel, cudaFuncAttributeMaxDynamicSharedMemorySize, 81920);
    cudaFuncSetAttribute(gemm_kernel, cudaFuncAttributeMaxDynamicSharedMemorySize, 98304);

    long long abase;
    int write_edges;
    if (out_size == (long long)NN * NN) { abase = 0; write_edges = 0; }
    else { abase = 3LL * NN * TOPK; write_edges = 1; }

    prep_kernel<<<dim3(NN / 32, 2), 256, 81920>>>(E1, W1, b1, E2, W2, b2);
    gemm_kernel<<<dim3(128, 64), 256, 98304>>>(out + abase);
    topk_kernel<<<NN, 256>>>(out, abase, write_edges);
}